// round 2
// baseline (speedup 1.0000x reference)
#include <cuda_runtime.h>
#include <cstdint>
#include <math_constants.h>

// ---------------------------------------------------------------------------
// spk_vq_vae_resnet: VQ codebook assign + EMA update + straight-through out.
//
// Inputs  (metadata order): Z [N=65536, D=128] f32, dict_val [K=2048, D=128] f32,
//                           dict_cnt [K] f32
// Outputs (concatenated f32): st_out [N*D], commit_loss [1], w_new [K*D], c_new [K]
//
// Pipeline:
//   0. zero scratch (counts/sums/loss)
//   1. w2[k] = sum(W[k]^2)
//   2. argmin kernel: fp32 tiled GEMM Z@W^T with running (min,idx) epilogue,
//      replicating reference rounding: dist = (z2 - 2*zw) + w2, first-index ties
//   3. scatter: counts (int atomics) + sums (fixed-point int64 atomics; exact
//      and deterministic across graph replays)
//   4. finalize: c_new / w_new with __f*_rn ops matching jnp op order
//   5. gather: st_out = z + (w_new[i]-z); commit loss accumulated in double
//   6. write loss
// ---------------------------------------------------------------------------

#define VQ_ALPHA 0.99f
#define VQ_OMA   0.01f   // float(1.0 - 0.99) == 0.01f

constexpr int D    = 128;
constexpr int NMAX = 65536;
constexpr int KMAX = 2048;
constexpr int BM   = 64;    // rows per block
constexpr int BK   = 64;    // codes per k-tile
constexpr int LDSM = 132;   // padded row stride (floats): 16B-aligned, low-conflict

__device__ int       g_idx[NMAX];
__device__ int       g_counts[KMAX];
__device__ long long g_sumsfx[KMAX * D];   // fixed-point 2^20
__device__ double    g_loss;
__device__ float     g_w2[KMAX];

// ---------------------------------------------------------------------------

__global__ void zero_kernel(int K) {
    int i = blockIdx.x * blockDim.x + threadIdx.x;
    int stride = gridDim.x * blockDim.x;
    for (int j = i; j < K * D; j += stride) g_sumsfx[j] = 0LL;
    for (int j = i; j < K; j += stride)     g_counts[j] = 0;
    if (i == 0) g_loss = 0.0;
}

__global__ void w2_kernel(const float* __restrict__ W, int K) {
    int warp = (blockIdx.x * blockDim.x + threadIdx.x) >> 5;
    int lane = threadIdx.x & 31;
    if (warp >= K) return;
    const float* w = W + (size_t)warp * D;
    float s = 0.f;
    #pragma unroll
    for (int q = 0; q < 4; q++) {
        float v = w[lane + 32 * q];
        s = __fadd_rn(s, __fmul_rn(v, v));
    }
    #pragma unroll
    for (int off = 16; off; off >>= 1)
        s = __fadd_rn(s, __shfl_xor_sync(0xffffffffu, s, off));
    if (lane == 0) g_w2[warp] = s;
}

// ---------------------------------------------------------------------------

__device__ __forceinline__ void cp_async16(void* smem_dst, const void* gmem_src) {
    uint32_t s = (uint32_t)__cvta_generic_to_shared(smem_dst);
    asm volatile("cp.async.cg.shared.global [%0], [%1], 16;\n" :: "r"(s), "l"(gmem_src));
}
__device__ __forceinline__ void cp_commit() {
    asm volatile("cp.async.commit_group;\n");
}
template <int NN>
__device__ __forceinline__ void cp_wait() {
    asm volatile("cp.async.wait_group %0;\n" :: "n"(NN));
}

// 64 rows x all K codes per block. 256 threads as 16(tc) x 16(tr), 4x4 microtile.
// Thread (tr,tc) owns rows {tr+16i} and codes {tile*64 + tc+16j}.
__global__ __launch_bounds__(256, 2)
void argmin_kernel(const float* __restrict__ Z, const float* __restrict__ W, int K) {
    extern __shared__ float smem[];
    float* Zs  = smem;                     // [BM][LDSM]
    float* Ws  = Zs + BM * LDSM;           // [2][BK][LDSM]
    float* w2s = Ws + 2 * BK * LDSM;       // [KMAX]
    float* z2s = w2s + KMAX;               // [BM]

    const int tid  = threadIdx.x;
    const int tc   = tid & 15;
    const int tr   = tid >> 4;
    const int row0 = blockIdx.x * BM;

    // Load Z tile (kept resident for the whole block)
    for (int i = tid; i < BM * (D / 4); i += 256) {
        int r = i >> 5, c = i & 31;
        float4 v = *(const float4*)(Z + (size_t)(row0 + r) * D + c * 4);
        *(float4*)&Zs[r * LDSM + c * 4] = v;
    }
    // Stage all w2 into smem
    for (int i = tid; i < K; i += 256) w2s[i] = g_w2[i];

    // Prefetch W tile 0
    for (int i = tid; i < BK * (D / 4); i += 256) {
        int r = i >> 5, c = i & 31;
        cp_async16(&Ws[r * LDSM + c * 4], W + (size_t)r * D + c * 4);
    }
    cp_commit();
    __syncthreads();

    // z2 per row (fp32, mul-then-add like reference's Z*Z sum)
    if (tid < BM) {
        const float* zr = &Zs[tid * LDSM];
        float s = 0.f;
        #pragma unroll 8
        for (int d = 0; d < D; d++) s = __fadd_rn(s, __fmul_rn(zr[d], zr[d]));
        z2s[tid] = s;
    }

    float bestv[4] = {CUDART_INF_F, CUDART_INF_F, CUDART_INF_F, CUDART_INF_F};
    int   besti[4] = {0, 0, 0, 0};

    const int ntiles = K / BK;
    for (int t = 0; t < ntiles; t++) {
        // Prefetch next tile into the other buffer
        if (t + 1 < ntiles) {
            const float* Wt = W + (size_t)(t + 1) * BK * D;
            float* dst = Ws + ((t + 1) & 1) * BK * LDSM;
            for (int i = tid; i < BK * (D / 4); i += 256) {
                int r = i >> 5, c = i & 31;
                cp_async16(&dst[r * LDSM + c * 4], Wt + (size_t)r * D + c * 4);
            }
            cp_commit();
            cp_wait<1>();
        } else {
            cp_wait<0>();
        }
        __syncthreads();   // tile t ready in all threads' view; z2s ready (t==0)

        const float* Wb = Ws + (t & 1) * BK * LDSM;
        float acc[4][4];
        #pragma unroll
        for (int i = 0; i < 4; i++)
            #pragma unroll
            for (int j = 0; j < 4; j++) acc[i][j] = 0.f;

        #pragma unroll 4
        for (int dq = 0; dq < D / 4; dq++) {
            float4 a[4], b[4];
            #pragma unroll
            for (int i = 0; i < 4; i++)
                a[i] = *(const float4*)&Zs[(tr + 16 * i) * LDSM + 4 * dq];
            #pragma unroll
            for (int j = 0; j < 4; j++)
                b[j] = *(const float4*)&Wb[(tc + 16 * j) * LDSM + 4 * dq];
            #pragma unroll
            for (int i = 0; i < 4; i++)
                #pragma unroll
                for (int j = 0; j < 4; j++) {
                    float s = acc[i][j];
                    s = fmaf(a[i].x, b[j].x, s);
                    s = fmaf(a[i].y, b[j].y, s);
                    s = fmaf(a[i].z, b[j].z, s);
                    s = fmaf(a[i].w, b[j].w, s);
                    acc[i][j] = s;
                }
        }

        // Epilogue: dist = (z2 - 2*zw) + w2 with reference op order + rounding,
        // strict < keeps first (lowest) index on ties.
        #pragma unroll
        for (int j = 0; j < 4; j++) {
            int code = t * BK + tc + 16 * j;
            float w2 = w2s[code];
            #pragma unroll
            for (int i = 0; i < 4; i++) {
                float dist = __fadd_rn(
                    __fsub_rn(z2s[tr + 16 * i], __fmul_rn(2.f, acc[i][j])), w2);
                if (dist < bestv[i] || (dist == bestv[i] && code < besti[i])) {
                    bestv[i] = dist;
                    besti[i] = code;
                }
            }
        }
        __syncthreads();   // protect Ws buffer before next prefetch overwrites
    }

    // Reduce (val,idx) across the 16 tc-lanes sharing each row (xor offsets < 16
    // stay within the same 16-lane half of the warp).
    #pragma unroll
    for (int i = 0; i < 4; i++) {
        float v = bestv[i];
        int  ix = besti[i];
        #pragma unroll
        for (int off = 8; off; off >>= 1) {
            float v2 = __shfl_xor_sync(0xffffffffu, v, off);
            int   i2 = __shfl_xor_sync(0xffffffffu, ix, off);
            if (v2 < v || (v2 == v && i2 < ix)) { v = v2; ix = i2; }
        }
        if (tc == 0) g_idx[row0 + tr + 16 * i] = ix;
    }
}

// ---------------------------------------------------------------------------

// One warp per row: counts + fixed-point sums (deterministic, exact scale 2^20).
// Each lane reads a float4 (coalesced LDG.128 across the warp).
__global__ void scatter_kernel(const float* __restrict__ Z, int N) {
    int warp = (blockIdx.x * blockDim.x + threadIdx.x) >> 5;
    int lane = threadIdx.x & 31;
    if (warp >= N) return;
    int j = g_idx[warp];
    if (lane == 0) atomicAdd(&g_counts[j], 1);
    const float4* zr = (const float4*)(Z + (size_t)warp * D);
    float4 v = zr[lane];   // 32 lanes x 4 floats = 128 = D
    long long base = (long long)j * D + lane * 4;
    unsigned long long* s = (unsigned long long*)g_sumsfx;
    atomicAdd(&s[base + 0], (unsigned long long)(long long)llrintf(v.x * 1048576.0f));
    atomicAdd(&s[base + 1], (unsigned long long)(long long)llrintf(v.y * 1048576.0f));
    atomicAdd(&s[base + 2], (unsigned long long)(long long)llrintf(v.z * 1048576.0f));
    atomicAdd(&s[base + 3], (unsigned long long)(long long)llrintf(v.w * 1048576.0f));
}

__global__ void finalize_kernel(const float* __restrict__ Wold,
                                const float* __restrict__ Cold,
                                float* __restrict__ out_w,
                                float* __restrict__ out_c, int K) {
    int k = blockIdx.x;
    int d = threadIdx.x;
    int cnts = g_counts[k];
    float c_old = Cold[k];
    float c_new = (cnts > 0)
        ? __fadd_rn(__fmul_rn(VQ_ALPHA, c_old), __fmul_rn(VQ_OMA, (float)cnts))
        : c_old;
    if (d == 0) out_c[k] = c_new;

    float w = Wold[(size_t)k * D + d];
    float wn = w;
    if (cnts > 0) {
        float s  = (float)((double)g_sumsfx[(size_t)k * D + d] * (1.0 / 1048576.0));
        float cm = fmaxf(c_new, 1e-12f);
        wn = __fadd_rn(__fmul_rn(VQ_ALPHA, w),
                       __fdiv_rn(__fmul_rn(VQ_OMA, s), cm));
    }
    out_w[(size_t)k * D + d] = wn;
}

// st_out = z + (w_new[i]-z)  (two fp32 roundings like the reference),
// commit loss partial sums -> double atomic (one per block).
__global__ void gather_loss_kernel(const float* __restrict__ Z,
                                   const float* __restrict__ Wn,
                                   float* __restrict__ out_st, int N) {
    int d = threadIdx.x;
    float accl = 0.f;
    for (int n = blockIdx.x; n < N; n += gridDim.x) {
        int j = g_idx[n];
        float w = Wn[(size_t)j * D + d];
        float z = Z[(size_t)n * D + d];
        out_st[(size_t)n * D + d] = __fadd_rn(z, __fsub_rn(w, z));
        float df = __fsub_rn(z, w);
        accl = fmaf(df, df, accl);
    }
    __shared__ float red[4];
    float s = accl;
    #pragma unroll
    for (int off = 16; off; off >>= 1) s += __shfl_xor_sync(0xffffffffu, s, off);
    if ((d & 31) == 0) red[d >> 5] = s;
    __syncthreads();
    if (d == 0) {
        float tot = (red[0] + red[1]) + (red[2] + red[3]);
        atomicAdd(&g_loss, (double)tot);
    }
}

__global__ void loss_write_kernel(float* out_loss, int N) {
    *out_loss = (float)(g_loss / (double)N);
}

// ---------------------------------------------------------------------------

extern "C" void kernel_launch(void* const* d_in, const int* in_sizes, int n_in,
                              void* d_out, int out_size) {
    const float* Z = (const float*)d_in[0];
    const float* W = (const float*)d_in[1];
    const float* C = (const float*)d_in[2];
    const int N = in_sizes[0] / D;       // 65536
    const int K = in_sizes[2];           // 2048

    float* out      = (float*)d_out;
    float* out_st   = out;                           // [N*D]
    float* out_loss = out + (size_t)N * D;           // [1]
    float* out_w    = out_loss + 1;                  // [K*D]
    float* out_c    = out_w + (size_t)K * D;         // [K]

    zero_kernel<<<256, 256>>>(K);
    w2_kernel<<<(K * 32 + 255) / 256, 256>>>(W, K);

    size_t smem = (size_t)(BM * LDSM + 2 * BK * LDSM + KMAX + BM) * sizeof(float);
    static bool attr_done = false;
    if (!attr_done) {
        cudaFuncSetAttribute(argmin_kernel,
                             cudaFuncAttributeMaxDynamicSharedMemorySize, (int)smem);
        attr_done = true;
    }
    argmin_kernel<<<N / BM, 256, smem>>>(Z, W, K);

    scatter_kernel<<<N / 8, 256>>>(Z, N);
    finalize_kernel<<<K, D>>>(W, C, out_w, out_c, K);
    gather_loss_kernel<<<2048, D>>>(Z, out_w, out_st, N);
    loss_write_kernel<<<1, 1>>>(out_loss, N);
}

// round 4
// speedup vs baseline: 1.1708x; 1.1708x over previous
#include <cuda_runtime.h>
#include <cuda_fp16.h>
#include <cstdint>
#include <math_constants.h>

// ---------------------------------------------------------------------------
// spk_vq_vae_resnet — fp16 mma.sync round (compute_100-safe: NO tcgen05).
// argmin via single-pass fp16 HMMA GEMM + top-3 band + 2-tier exact rescue.
// Outputs (concat f32): st_out [N*D], commit_loss [1], w_new [K*D], c_new [K]
// ---------------------------------------------------------------------------

#define VQ_ALPHA 0.99f
#define VQ_OMA   0.01f

constexpr int D    = 128;
constexpr int NMAX = 65536;
constexpr int KMAX = 2048;
constexpr int NTILE = 16;          // code tiles of 128
constexpr float BAND = 1e-3f;

// ---- device scratch -------------------------------------------------------
__device__ __align__(16) __half g_Zh[NMAX * D];
__device__ __align__(16) __half g_Wh[KMAX * D];
__device__ float     g_w2[KMAX];
__device__ int       g_idx[NMAX];
__device__ int       g_f1row[NMAX], g_f1a[NMAX], g_f1b[NMAX];
__device__ int       g_f2row[NMAX];
__device__ int       g_n1, g_n2;
__device__ int       g_counts[KMAX];
__device__ long long g_sumsfx[KMAX * D];   // fixed-point 2^20
__device__ double    g_loss;

// ---- helpers --------------------------------------------------------------
__device__ __forceinline__ uint32_t smem_u32(const void* p) {
    uint32_t a;
    asm("{ .reg .u64 t; cvta.to.shared.u64 t, %1; cvt.u32.u64 %0, t; }"
        : "=r"(a) : "l"(p));
    return a;
}
__device__ __forceinline__ void cp_async16(uint32_t smem_dst, const void* gsrc) {
    asm volatile("cp.async.cg.shared.global [%0], [%1], 16;" :: "r"(smem_dst), "l"(gsrc));
}
__device__ __forceinline__ void cp_commit() { asm volatile("cp.async.commit_group;"); }
template <int NN>
__device__ __forceinline__ void cp_wait() { asm volatile("cp.async.wait_group %0;" :: "n"(NN)); }

__device__ __forceinline__ void ldsm4(uint32_t& r0, uint32_t& r1, uint32_t& r2,
                                      uint32_t& r3, uint32_t addr) {
    asm volatile("ldmatrix.sync.aligned.m8n8.x4.shared.b16 {%0,%1,%2,%3}, [%4];"
                 : "=r"(r0), "=r"(r1), "=r"(r2), "=r"(r3) : "r"(addr));
}
__device__ __forceinline__ void mma16816(float* c, uint32_t a0, uint32_t a1,
                                         uint32_t a2, uint32_t a3,
                                         uint32_t b0, uint32_t b1) {
    asm volatile(
        "mma.sync.aligned.m16n8k16.row.col.f32.f16.f16.f32 "
        "{%0,%1,%2,%3}, {%4,%5,%6,%7}, {%8,%9}, {%0,%1,%2,%3};"
        : "+f"(c[0]), "+f"(c[1]), "+f"(c[2]), "+f"(c[3])
        : "r"(a0), "r"(a1), "r"(a2), "r"(a3), "r"(b0), "r"(b1));
}

// top-3 insert with lowest-index tie preference
__device__ __forceinline__ void ins3(float s, int c,
                                     float& b1, int& i1, float& b2, int& i2,
                                     float& b3, int& i3) {
    if (s < b1 || (s == b1 && c < i1)) {
        b3 = b2; i3 = i2; b2 = b1; i2 = i1; b1 = s; i1 = c;
    } else if (s < b2 || (s == b2 && c < i2)) {
        b3 = b2; i3 = i2; b2 = s; i2 = c;
    } else if (s < b3 || (s == b3 && c < i3)) {
        b3 = s; i3 = c;
    }
}

// ---------------------------------------------------------------------------

__global__ void zero_kernel(int K) {
    int i = blockIdx.x * blockDim.x + threadIdx.x;
    int stride = gridDim.x * blockDim.x;
    for (int j = i; j < K * D; j += stride) g_sumsfx[j] = 0LL;
    for (int j = i; j < K; j += stride)     g_counts[j] = 0;
    if (i == 0) { g_loss = 0.0; g_n1 = 0; g_n2 = 0; }
}

// fp32 -> fp16 conversion for Z and W; w2 for W rows.
__global__ void prep_kernel(const float* __restrict__ Z,
                            const float* __restrict__ W, int N, int K) {
    int g    = (blockIdx.x * blockDim.x + threadIdx.x) >> 5;
    int lane = threadIdx.x & 31;
    if (g >= N + K) return;
    const float* src;
    __half* dst;
    bool isW = (g >= N);
    if (!isW) { src = Z + (size_t)g * D;        dst = g_Zh + (size_t)g * D; }
    else      { src = W + (size_t)(g - N) * D;  dst = g_Wh + (size_t)(g - N) * D; }
    float4 v = ((const float4*)src)[lane];
    __half2 h01 = __floats2half2_rn(v.x, v.y);
    __half2 h23 = __floats2half2_rn(v.z, v.w);
    uint2 u = { *(uint32_t*)&h01, *(uint32_t*)&h23 };
    *(uint2*)(dst + lane * 4) = u;
    if (isW) {
        float s = 0.f;
        s = fmaf(v.x, v.x, s); s = fmaf(v.y, v.y, s);
        s = fmaf(v.z, v.z, s); s = fmaf(v.w, v.w, s);
        #pragma unroll
        for (int off = 16; off; off >>= 1) s += __shfl_xor_sync(0xffffffffu, s, off);
        if (lane == 0) g_w2[g - N] = s;
    }
}

// ---- fp16 HMMA argmin ------------------------------------------------------
// smem: Zs 32KB | Bs 2x32KB | w2s 8KB
constexpr int SM_Z  = 0;
constexpr int SM_B0 = 32768;
constexpr int SM_W2 = 98304;
constexpr int SMEM_ARG = SM_W2 + KMAX * 4;   // 106496 bytes

// swizzled chunk store address: row-major rows of 16 chunks (16B each)
__device__ __forceinline__ uint32_t sw_addr(uint32_t base, int r, int c) {
    return base + r * 256 + ((c ^ (r & 7)) << 4);
}

__global__ __launch_bounds__(256, 1)
void argmin_hmma_kernel() {
    extern __shared__ char sm[];
    const uint32_t sb = smem_u32(sm);
    float* w2s = (float*)(sm + SM_W2);
    const int tid  = threadIdx.x;
    const int lane = tid & 31;
    const int wid  = tid >> 5;
    const int warpRow = wid * 16;
    const int row0 = blockIdx.x * 128;

    for (int i = tid; i < KMAX; i += 256) w2s[i] = g_w2[i];

    // group 0: Z tile + B tile 0
    for (int i = tid; i < 2048; i += 256) {
        int r = i >> 4, c = i & 15;
        cp_async16(sw_addr(sb + SM_Z, r, c), g_Zh + (size_t)(row0 + r) * D + c * 8);
    }
    for (int i = tid; i < 2048; i += 256) {
        int r = i >> 4, c = i & 15;
        cp_async16(sw_addr(sb + SM_B0, r, c), g_Wh + (size_t)r * D + c * 8);
    }
    cp_commit();
    // group 1: B tile 1
    for (int i = tid; i < 2048; i += 256) {
        int r = i >> 4, c = i & 15;
        cp_async16(sw_addr(sb + SM_B0 + 32768, r, c),
                   g_Wh + (size_t)(128 + r) * D + c * 8);
    }
    cp_commit();

    float B1[2] = {CUDART_INF_F, CUDART_INF_F};
    float B2[2] = {CUDART_INF_F, CUDART_INF_F};
    float B3[2] = {CUDART_INF_F, CUDART_INF_F};
    int   I1[2] = {0x7fffffff, 0x7fffffff};
    int   I2[2] = {0x7fffffff, 0x7fffffff};
    int   I3[2] = {0x7fffffff, 0x7fffffff};

    const int m  = lane >> 3;
    const int r8 = lane & 7;

    for (int t = 0; t < NTILE; t++) {
        if (t < NTILE - 1) cp_wait<1>(); else cp_wait<0>();
        __syncthreads();
        const uint32_t bbase = sb + SM_B0 + (t & 1) * 32768;

        float acc[16][4];
        #pragma unroll
        for (int f = 0; f < 16; f++)
            #pragma unroll
            for (int q = 0; q < 4; q++) acc[f][q] = 0.f;

        #pragma unroll
        for (int ks = 0; ks < 8; ks++) {
            uint32_t a0, a1, a2, a3;
            {
                int row = warpRow + ((m & 1) << 3) + r8;
                int ch  = 2 * ks + (m >> 1);
                ldsm4(a0, a1, a2, a3, sw_addr(sb + SM_Z, row, ch));
            }
            #pragma unroll
            for (int nf = 0; nf < 16; nf += 2) {
                uint32_t c0, c1, c2, c3;
                {
                    int code = nf * 8 + ((m >> 1) << 3) + r8;
                    int ch   = 2 * ks + (m & 1);
                    ldsm4(c0, c1, c2, c3, sw_addr(bbase, code, ch));
                }
                mma16816(acc[nf],     a0, a1, a2, a3, c0, c1);
                mma16816(acc[nf + 1], a0, a1, a2, a3, c2, c3);
            }
        }

        // epilogue: score s = w2 - 2*zw ; rows r0 = warpRow+(lane>>2), r1 = r0+8
        #pragma unroll
        for (int f = 0; f < 16; f++) {
            int cb0 = t * 128 + f * 8 + 2 * (lane & 3);
            float w2a = w2s[cb0], w2b = w2s[cb0 + 1];
            float s;
            s = fmaf(-2.f, acc[f][0], w2a);
            ins3(s, cb0,     B1[0], I1[0], B2[0], I2[0], B3[0], I3[0]);
            s = fmaf(-2.f, acc[f][1], w2b);
            ins3(s, cb0 + 1, B1[0], I1[0], B2[0], I2[0], B3[0], I3[0]);
            s = fmaf(-2.f, acc[f][2], w2a);
            ins3(s, cb0,     B1[1], I1[1], B2[1], I2[1], B3[1], I3[1]);
            s = fmaf(-2.f, acc[f][3], w2b);
            ins3(s, cb0 + 1, B1[1], I1[1], B2[1], I2[1], B3[1], I3[1]);
        }
        __syncthreads();

        if (t < NTILE - 2) {
            const __half* src = g_Wh + (size_t)(t + 2) * 128 * D;
            uint32_t dstb = sb + SM_B0 + (t & 1) * 32768;
            for (int i = tid; i < 2048; i += 256) {
                int r = i >> 4, c = i & 15;
                cp_async16(sw_addr(dstb, r, c), src + (size_t)r * D + c * 8);
            }
            cp_commit();
        }
    }

    // merge across the 4 lanes of each quad (same rows)
    #pragma unroll
    for (int off = 1; off <= 2; off <<= 1) {
        #pragma unroll
        for (int r = 0; r < 2; r++) {
            float v1 = __shfl_xor_sync(0xffffffffu, B1[r], off);
            int   j1 = __shfl_xor_sync(0xffffffffu, I1[r], off);
            float v2 = __shfl_xor_sync(0xffffffffu, B2[r], off);
            int   j2 = __shfl_xor_sync(0xffffffffu, I2[r], off);
            float v3 = __shfl_xor_sync(0xffffffffu, B3[r], off);
            int   j3 = __shfl_xor_sync(0xffffffffu, I3[r], off);
            ins3(v1, j1, B1[r], I1[r], B2[r], I2[r], B3[r], I3[r]);
            ins3(v2, j2, B1[r], I1[r], B2[r], I2[r], B3[r], I3[r]);
            ins3(v3, j3, B1[r], I1[r], B2[r], I2[r], B3[r], I3[r]);
        }
    }

    if ((lane & 3) == 0) {
        #pragma unroll
        for (int r = 0; r < 2; r++) {
            int row = row0 + warpRow + (lane >> 2) + r * 8;
            g_idx[row] = I1[r];
            if (__fsub_rn(B3[r], B1[r]) < BAND) {
                int p = atomicAdd(&g_n2, 1);
                g_f2row[p] = row;
            } else if (__fsub_rn(B2[r], B1[r]) < BAND) {
                int p = atomicAdd(&g_n1, 1);
                g_f1row[p] = row; g_f1a[p] = I1[r]; g_f1b[p] = I2[r];
            }
        }
    }
}

// ---- tier 1: exact fp32 compare of the two candidates ----------------------
__global__ void tier1_kernel(const float* __restrict__ Z,
                             const float* __restrict__ W) {
    int n1 = g_n1;
    for (int e = blockIdx.x * blockDim.x + threadIdx.x; e < n1;
         e += gridDim.x * blockDim.x) {
        int row = g_f1row[e], ca = g_f1a[e], cb = g_f1b[e];
        const float* z  = Z + (size_t)row * D;
        const float* wa = W + (size_t)ca * D;
        const float* wb = W + (size_t)cb * D;
        float z2 = 0.f, da = 0.f, db = 0.f;
        #pragma unroll 8
        for (int d = 0; d < D; d++) {
            float zd = z[d];
            z2 = __fadd_rn(z2, __fmul_rn(zd, zd));
            da = fmaf(zd, wa[d], da);
            db = fmaf(zd, wb[d], db);
        }
        float dista = __fadd_rn(__fsub_rn(z2, __fmul_rn(2.f, da)), g_w2[ca]);
        float distb = __fadd_rn(__fsub_rn(z2, __fmul_rn(2.f, db)), g_w2[cb]);
        g_idx[row] = (distb < dista || (distb == dista && cb < ca)) ? cb : ca;
    }
}

// ---- tier 2: full-K exact recompute (rare rows) ----------------------------
__global__ void tier2_kernel(const float* __restrict__ Z,
                             const float* __restrict__ W) {
    __shared__ float zrow[D];
    __shared__ float rv[256];
    __shared__ int   ri[256];
    const int tid = threadIdx.x;
    int n2 = g_n2;
    for (int f = blockIdx.x; f < n2; f += gridDim.x) {
        int row = g_f2row[f];
        if (tid < 32) {
            float4 v = ((const float4*)(Z + (size_t)row * D))[tid];
            *(float4*)&zrow[tid * 4] = v;
        }
        __syncthreads();
        float z2 = 0.f;
        #pragma unroll 8
        for (int d = 0; d < D; d++) z2 = __fadd_rn(z2, __fmul_rn(zrow[d], zrow[d]));
        float bv = CUDART_INF_F; int bidx = 0x7fffffff;
        for (int c = tid; c < KMAX; c += 256) {
            const float* w = W + (size_t)c * D;
            float acc = 0.f;
            #pragma unroll 8
            for (int d = 0; d < D; d++) acc = fmaf(zrow[d], w[d], acc);
            float dist = __fadd_rn(__fsub_rn(z2, __fmul_rn(2.f, acc)), g_w2[c]);
            if (dist < bv || (dist == bv && c < bidx)) { bv = dist; bidx = c; }
        }
        rv[tid] = bv; ri[tid] = bidx;
        __syncthreads();
        for (int s = 128; s; s >>= 1) {
            if (tid < s) {
                float v2 = rv[tid + s]; int i2 = ri[tid + s];
                if (v2 < rv[tid] || (v2 == rv[tid] && i2 < ri[tid])) {
                    rv[tid] = v2; ri[tid] = i2;
                }
            }
            __syncthreads();
        }
        if (tid == 0) g_idx[row] = ri[0];
        __syncthreads();
    }
}

// ---------------------------------------------------------------------------

__global__ void scatter_kernel(const float* __restrict__ Z, int N) {
    int warp = (blockIdx.x * blockDim.x + threadIdx.x) >> 5;
    int lane = threadIdx.x & 31;
    if (warp >= N) return;
    int j = g_idx[warp];
    if (lane == 0) atomicAdd(&g_counts[j], 1);
    float4 v = ((const float4*)(Z + (size_t)warp * D))[lane];
    long long base = (long long)j * D + lane * 4;
    unsigned long long* s = (unsigned long long*)g_sumsfx;
    atomicAdd(&s[base + 0], (unsigned long long)(long long)llrintf(v.x * 1048576.0f));
    atomicAdd(&s[base + 1], (unsigned long long)(long long)llrintf(v.y * 1048576.0f));
    atomicAdd(&s[base + 2], (unsigned long long)(long long)llrintf(v.z * 1048576.0f));
    atomicAdd(&s[base + 3], (unsigned long long)(long long)llrintf(v.w * 1048576.0f));
}

__global__ void finalize_kernel(const float* __restrict__ Wold,
                                const float* __restrict__ Cold,
                                float* __restrict__ out_w,
                                float* __restrict__ out_c, int K) {
    int k = blockIdx.x;
    int d = threadIdx.x;
    int cnts = g_counts[k];
    float c_old = Cold[k];
    float c_new = (cnts > 0)
        ? __fadd_rn(__fmul_rn(VQ_ALPHA, c_old), __fmul_rn(VQ_OMA, (float)cnts))
        : c_old;
    if (d == 0) out_c[k] = c_new;
    float w = Wold[(size_t)k * D + d];
    float wn = w;
    if (cnts > 0) {
        float s  = (float)((double)g_sumsfx[(size_t)k * D + d] * (1.0 / 1048576.0));
        float cm = fmaxf(c_new, 1e-12f);
        wn = __fadd_rn(__fmul_rn(VQ_ALPHA, w),
                       __fdiv_rn(__fmul_rn(VQ_OMA, s), cm));
    }
    out_w[(size_t)k * D + d] = wn;
}

__global__ void gather_loss_kernel(const float* __restrict__ Z,
                                   const float* __restrict__ Wn,
                                   float* __restrict__ out_st, int N) {
    int d = threadIdx.x;
    float accl = 0.f;
    for (int n = blockIdx.x; n < N; n += gridDim.x) {
        int j = g_idx[n];
        float w = Wn[(size_t)j * D + d];
        float z = Z[(size_t)n * D + d];
        out_st[(size_t)n * D + d] = __fadd_rn(z, __fsub_rn(w, z));
        float df = __fsub_rn(z, w);
        accl = fmaf(df, df, accl);
    }
    __shared__ float red[4];
    float s = accl;
    #pragma unroll
    for (int off = 16; off; off >>= 1) s += __shfl_xor_sync(0xffffffffu, s, off);
    if ((d & 31) == 0) red[d >> 5] = s;
    __syncthreads();
    if (d == 0) {
        float tot = (red[0] + red[1]) + (red[2] + red[3]);
        atomicAdd(&g_loss, (double)tot);
    }
}

__global__ void loss_write_kernel(float* out_loss, int N) {
    *out_loss = (float)(g_loss / (double)N);
}

// ---------------------------------------------------------------------------

extern "C" void kernel_launch(void* const* d_in, const int* in_sizes, int n_in,
                              void* d_out, int out_size) {
    const float* Z = (const float*)d_in[0];
    const float* W = (const float*)d_in[1];
    const float* C = (const float*)d_in[2];
    const int N = in_sizes[0] / D;       // 65536
    const int K = in_sizes[2];           // 2048

    float* out      = (float*)d_out;
    float* out_st   = out;                           // [N*D]
    float* out_loss = out + (size_t)N * D;           // [1]
    float* out_w    = out_loss + 1;                  // [K*D]
    float* out_c    = out_w + (size_t)K * D;         // [K]

    static bool attr_done = false;
    if (!attr_done) {
        cudaFuncSetAttribute(argmin_hmma_kernel,
                             cudaFuncAttributeMaxDynamicSharedMemorySize, SMEM_ARG);
        attr_done = true;
    }

    zero_kernel<<<256, 256>>>(K);
    prep_kernel<<<((N + K) * 32 + 255) / 256, 256>>>(Z, W, N, K);
    argmin_hmma_kernel<<<N / 128, 256, SMEM_ARG>>>();
    tier1_kernel<<<64, 256>>>(Z, W);
    tier2_kernel<<<128, 256>>>(Z, W);
    scatter_kernel<<<N / 8, 256>>>(Z, N);
    finalize_kernel<<<K, D>>>(W, C, out_w, out_c, K);
    gather_loss_kernel<<<2048, D>>>(Z, out_w, out_st, N);
    loss_write_kernel<<<1, 1>>>(out_loss, N);
}

// round 6
// speedup vs baseline: 1.6119x; 1.3767x over previous
#include <cuda_runtime.h>
#include <cuda_fp16.h>
#include <cstdint>
#include <math_constants.h>

// ---------------------------------------------------------------------------
// spk_vq_vae_resnet — fp16 mma.sync, occupancy-2 round (resubmit: infra fail).
// argmin via single-pass fp16 HMMA GEMM + top-3 band + 2-tier exact rescue.
// Outputs (concat f32): st_out [N*D], commit_loss [1], w_new [K*D], c_new [K]
// ---------------------------------------------------------------------------

#define VQ_ALPHA 0.99f
#define VQ_OMA   0.01f

constexpr int D    = 128;
constexpr int NMAX = 65536;
constexpr int KMAX = 2048;
constexpr int NTILE = 16;          // code tiles of 128
constexpr float BAND = 1e-3f;

// ---- device scratch -------------------------------------------------------
__device__ __align__(16) __half g_Zh[NMAX * D];
__device__ __align__(16) __half g_Wh[KMAX * D];
__device__ float     g_w2[KMAX];
__device__ int       g_idx[NMAX];
__device__ int       g_f1row[NMAX], g_f1a[NMAX], g_f1b[NMAX];
__device__ int       g_f2row[NMAX];
__device__ int       g_n1, g_n2;
__device__ int       g_counts[KMAX];
__device__ long long g_sumsfx[KMAX * D];   // fixed-point 2^20
__device__ double    g_loss;

// ---- helpers --------------------------------------------------------------
__device__ __forceinline__ uint32_t smem_u32(const void* p) {
    uint32_t a;
    asm("{ .reg .u64 t; cvta.to.shared.u64 t, %1; cvt.u32.u64 %0, t; }"
        : "=r"(a) : "l"(p));
    return a;
}
__device__ __forceinline__ void cp_async16(uint32_t smem_dst, const void* gsrc) {
    asm volatile("cp.async.cg.shared.global [%0], [%1], 16;" :: "r"(smem_dst), "l"(gsrc));
}
__device__ __forceinline__ void cp_commit() { asm volatile("cp.async.commit_group;"); }
template <int NN>
__device__ __forceinline__ void cp_wait() { asm volatile("cp.async.wait_group %0;" :: "n"(NN)); }

__device__ __forceinline__ void ldsm4(uint32_t& r0, uint32_t& r1, uint32_t& r2,
                                      uint32_t& r3, uint32_t addr) {
    asm volatile("ldmatrix.sync.aligned.m8n8.x4.shared.b16 {%0,%1,%2,%3}, [%4];"
                 : "=r"(r0), "=r"(r1), "=r"(r2), "=r"(r3) : "r"(addr));
}
__device__ __forceinline__ void mma16816(float* c, uint32_t a0, uint32_t a1,
                                         uint32_t a2, uint32_t a3,
                                         uint32_t b0, uint32_t b1) {
    asm volatile(
        "mma.sync.aligned.m16n8k16.row.col.f32.f16.f16.f32 "
        "{%0,%1,%2,%3}, {%4,%5,%6,%7}, {%8,%9}, {%0,%1,%2,%3};"
        : "+f"(c[0]), "+f"(c[1]), "+f"(c[2]), "+f"(c[3])
        : "r"(a0), "r"(a1), "r"(a2), "r"(a3), "r"(b0), "r"(b1));
}

// top-3 insert with lowest-index tie preference
__device__ __forceinline__ void ins3(float s, int c,
                                     float& b1, int& i1, float& b2, int& i2,
                                     float& b3, int& i3) {
    if (s < b1 || (s == b1 && c < i1)) {
        b3 = b2; i3 = i2; b2 = b1; i2 = i1; b1 = s; i1 = c;
    } else if (s < b2 || (s == b2 && c < i2)) {
        b3 = b2; i3 = i2; b2 = s; i2 = c;
    } else if (s < b3 || (s == b3 && c < i3)) {
        b3 = s; i3 = c;
    }
}

// ---------------------------------------------------------------------------

__global__ void zero_kernel(int K) {
    int i = blockIdx.x * blockDim.x + threadIdx.x;
    int stride = gridDim.x * blockDim.x;
    for (int j = i; j < K * D; j += stride) g_sumsfx[j] = 0LL;
    for (int j = i; j < K; j += stride)     g_counts[j] = 0;
    if (i == 0) { g_loss = 0.0; g_n1 = 0; g_n2 = 0; }
}

// fp32 -> fp16 conversion for Z and W; w2 for W rows.
__global__ void prep_kernel(const float* __restrict__ Z,
                            const float* __restrict__ W, int N, int K) {
    int g    = (blockIdx.x * blockDim.x + threadIdx.x) >> 5;
    int lane = threadIdx.x & 31;
    if (g >= N + K) return;
    const float* src;
    __half* dst;
    bool isW = (g >= N);
    if (!isW) { src = Z + (size_t)g * D;        dst = g_Zh + (size_t)g * D; }
    else      { src = W + (size_t)(g - N) * D;  dst = g_Wh + (size_t)(g - N) * D; }
    float4 v = ((const float4*)src)[lane];
    __half2 h01 = __floats2half2_rn(v.x, v.y);
    __half2 h23 = __floats2half2_rn(v.z, v.w);
    uint2 u = { *(uint32_t*)&h01, *(uint32_t*)&h23 };
    *(uint2*)(dst + lane * 4) = u;
    if (isW) {
        float s = 0.f;
        s = fmaf(v.x, v.x, s); s = fmaf(v.y, v.y, s);
        s = fmaf(v.z, v.z, s); s = fmaf(v.w, v.w, s);
        #pragma unroll
        for (int off = 16; off; off >>= 1) s += __shfl_xor_sync(0xffffffffu, s, off);
        if (lane == 0) g_w2[g - N] = s;
    }
}

// ---- fp16 HMMA argmin ------------------------------------------------------
// smem: Zs 32KB | Bs 2x32KB | w2s 8KB  = 106496 B -> 2 CTAs/SM (213KB < 228KB)
constexpr int SM_Z  = 0;
constexpr int SM_B0 = 32768;
constexpr int SM_W2 = 98304;
constexpr int SMEM_ARG = SM_W2 + KMAX * 4;   // 106496 bytes

// swizzled chunk store address: row-major rows of 16 chunks (16B each)
__device__ __forceinline__ uint32_t sw_addr(uint32_t base, int r, int c) {
    return base + r * 256 + ((c ^ (r & 7)) << 4);
}

__global__ __launch_bounds__(256, 2)
void argmin_hmma_kernel() {
    extern __shared__ char sm[];
    const uint32_t sb = smem_u32(sm);
    float* w2s = (float*)(sm + SM_W2);
    const int tid  = threadIdx.x;
    const int lane = tid & 31;
    const int wid  = tid >> 5;
    const int warpRow = wid * 16;
    const int row0 = blockIdx.x * 128;

    for (int i = tid; i < KMAX; i += 256) w2s[i] = g_w2[i];

    // group 0: Z tile + B tile 0
    for (int i = tid; i < 2048; i += 256) {
        int r = i >> 4, c = i & 15;
        cp_async16(sw_addr(sb + SM_Z, r, c), g_Zh + (size_t)(row0 + r) * D + c * 8);
    }
    for (int i = tid; i < 2048; i += 256) {
        int r = i >> 4, c = i & 15;
        cp_async16(sw_addr(sb + SM_B0, r, c), g_Wh + (size_t)r * D + c * 8);
    }
    cp_commit();
    // group 1: B tile 1
    for (int i = tid; i < 2048; i += 256) {
        int r = i >> 4, c = i & 15;
        cp_async16(sw_addr(sb + SM_B0 + 32768, r, c),
                   g_Wh + (size_t)(128 + r) * D + c * 8);
    }
    cp_commit();

    float B1[2] = {CUDART_INF_F, CUDART_INF_F};
    float B2[2] = {CUDART_INF_F, CUDART_INF_F};
    float B3[2] = {CUDART_INF_F, CUDART_INF_F};
    int   I1[2] = {0x7fffffff, 0x7fffffff};
    int   I2[2] = {0x7fffffff, 0x7fffffff};
    int   I3[2] = {0x7fffffff, 0x7fffffff};

    const int m  = lane >> 3;
    const int r8 = lane & 7;

    for (int t = 0; t < NTILE; t++) {
        if (t < NTILE - 1) cp_wait<1>(); else cp_wait<0>();
        __syncthreads();                       // B[t] visible to all warps
        const uint32_t bbase = sb + SM_B0 + (t & 1) * 32768;

        float acc[16][4];
        #pragma unroll
        for (int f = 0; f < 16; f++)
            #pragma unroll
            for (int q = 0; q < 4; q++) acc[f][q] = 0.f;

        #pragma unroll
        for (int ks = 0; ks < 8; ks++) {
            uint32_t a0, a1, a2, a3;
            {
                int row = warpRow + ((m & 1) << 3) + r8;
                int ch  = 2 * ks + (m >> 1);
                ldsm4(a0, a1, a2, a3, sw_addr(sb + SM_Z, row, ch));
            }
            #pragma unroll
            for (int nf = 0; nf < 16; nf += 2) {
                uint32_t c0, c1, c2, c3;
                {
                    int code = nf * 8 + ((m >> 1) << 3) + r8;
                    int ch   = 2 * ks + (m & 1);
                    ldsm4(c0, c1, c2, c3, sw_addr(bbase, code, ch));
                }
                mma16816(acc[nf],     a0, a1, a2, a3, c0, c1);
                mma16816(acc[nf + 1], a0, a1, a2, a3, c2, c3);
            }
        }

        __syncthreads();                       // all warps done reading B[t]

        // issue prefetch of tile t+2 into this buffer, then overlap w/ epilogue
        if (t < NTILE - 2) {
            const __half* src = g_Wh + (size_t)(t + 2) * 128 * D;
            uint32_t dstb = sb + SM_B0 + (t & 1) * 32768;
            for (int i = tid; i < 2048; i += 256) {
                int r = i >> 4, c = i & 15;
                cp_async16(sw_addr(dstb, r, c), src + (size_t)r * D + c * 8);
            }
            cp_commit();
        }

        // epilogue: score s = w2 - 2*zw ; rows r0 = warpRow+(lane>>2), r1 = r0+8
        #pragma unroll
        for (int f = 0; f < 16; f++) {
            int cb0 = t * 128 + f * 8 + 2 * (lane & 3);
            float w2a = w2s[cb0], w2b = w2s[cb0 + 1];
            float s;
            s = fmaf(-2.f, acc[f][0], w2a);
            ins3(s, cb0,     B1[0], I1[0], B2[0], I2[0], B3[0], I3[0]);
            s = fmaf(-2.f, acc[f][1], w2b);
            ins3(s, cb0 + 1, B1[0], I1[0], B2[0], I2[0], B3[0], I3[0]);
            s = fmaf(-2.f, acc[f][2], w2a);
            ins3(s, cb0,     B1[1], I1[1], B2[1], I2[1], B3[1], I3[1]);
            s = fmaf(-2.f, acc[f][3], w2b);
            ins3(s, cb0 + 1, B1[1], I1[1], B2[1], I2[1], B3[1], I3[1]);
        }
    }

    // merge across the 4 lanes of each quad (same rows)
    #pragma unroll
    for (int off = 1; off <= 2; off <<= 1) {
        #pragma unroll
        for (int r = 0; r < 2; r++) {
            float v1 = __shfl_xor_sync(0xffffffffu, B1[r], off);
            int   j1 = __shfl_xor_sync(0xffffffffu, I1[r], off);
            float v2 = __shfl_xor_sync(0xffffffffu, B2[r], off);
            int   j2 = __shfl_xor_sync(0xffffffffu, I2[r], off);
            float v3 = __shfl_xor_sync(0xffffffffu, B3[r], off);
            int   j3 = __shfl_xor_sync(0xffffffffu, I3[r], off);
            ins3(v1, j1, B1[r], I1[r], B2[r], I2[r], B3[r], I3[r]);
            ins3(v2, j2, B1[r], I1[r], B2[r], I2[r], B3[r], I3[r]);
            ins3(v3, j3, B1[r], I1[r], B2[r], I2[r], B3[r], I3[r]);
        }
    }

    if ((lane & 3) == 0) {
        #pragma unroll
        for (int r = 0; r < 2; r++) {
            int row = row0 + warpRow + (lane >> 2) + r * 8;
            g_idx[row] = I1[r];
            if (__fsub_rn(B3[r], B1[r]) < BAND) {
                int p = atomicAdd(&g_n2, 1);
                g_f2row[p] = row;
            } else if (__fsub_rn(B2[r], B1[r]) < BAND) {
                int p = atomicAdd(&g_n1, 1);
                g_f1row[p] = row; g_f1a[p] = I1[r]; g_f1b[p] = I2[r];
            }
        }
    }
}

// ---- tier 1: exact fp32 compare of the two candidates ----------------------
// One warp per flagged row; lanes split D with float4 (coalesced), warp-reduce.
__global__ void tier1_kernel(const float* __restrict__ Z,
                             const float* __restrict__ W) {
    int n1 = g_n1;
    int wg = (blockIdx.x * blockDim.x + threadIdx.x) >> 5;
    int lane = threadIdx.x & 31;
    int nwarps = (gridDim.x * blockDim.x) >> 5;
    for (int e = wg; e < n1; e += nwarps) {
        int row = g_f1row[e], ca = g_f1a[e], cb = g_f1b[e];
        float4 zv = ((const float4*)(Z + (size_t)row * D))[lane];
        float4 av = ((const float4*)(W + (size_t)ca * D))[lane];
        float4 bv = ((const float4*)(W + (size_t)cb * D))[lane];
        float z2 = 0.f, da = 0.f, db = 0.f;
        z2 = fmaf(zv.x, zv.x, z2); z2 = fmaf(zv.y, zv.y, z2);
        z2 = fmaf(zv.z, zv.z, z2); z2 = fmaf(zv.w, zv.w, z2);
        da = fmaf(zv.x, av.x, da); da = fmaf(zv.y, av.y, da);
        da = fmaf(zv.z, av.z, da); da = fmaf(zv.w, av.w, da);
        db = fmaf(zv.x, bv.x, db); db = fmaf(zv.y, bv.y, db);
        db = fmaf(zv.z, bv.z, db); db = fmaf(zv.w, bv.w, db);
        #pragma unroll
        for (int off = 16; off; off >>= 1) {
            z2 += __shfl_xor_sync(0xffffffffu, z2, off);
            da += __shfl_xor_sync(0xffffffffu, da, off);
            db += __shfl_xor_sync(0xffffffffu, db, off);
        }
        if (lane == 0) {
            float dista = __fadd_rn(__fsub_rn(z2, __fmul_rn(2.f, da)), g_w2[ca]);
            float distb = __fadd_rn(__fsub_rn(z2, __fmul_rn(2.f, db)), g_w2[cb]);
            g_idx[row] = (distb < dista || (distb == dista && cb < ca)) ? cb : ca;
        }
    }
}

// ---- tier 2: full-K exact recompute (rare rows) ----------------------------
__global__ void tier2_kernel(const float* __restrict__ Z,
                             const float* __restrict__ W) {
    __shared__ float zrow[D];
    __shared__ float rv[256];
    __shared__ int   ri[256];
    const int tid = threadIdx.x;
    int n2 = g_n2;
    for (int f = blockIdx.x; f < n2; f += gridDim.x) {
        int row = g_f2row[f];
        if (tid < 32) {
            float4 v = ((const float4*)(Z + (size_t)row * D))[tid];
            *(float4*)&zrow[tid * 4] = v;
        }
        __syncthreads();
        float z2 = 0.f;
        #pragma unroll 8
        for (int d = 0; d < D; d++) z2 = __fadd_rn(z2, __fmul_rn(zrow[d], zrow[d]));
        float bv = CUDART_INF_F; int bidx = 0x7fffffff;
        for (int c = tid; c < KMAX; c += 256) {
            const float* w = W + (size_t)c * D;
            float acc = 0.f;
            #pragma unroll 8
            for (int d = 0; d < D; d++) acc = fmaf(zrow[d], w[d], acc);
            float dist = __fadd_rn(__fsub_rn(z2, __fmul_rn(2.f, acc)), g_w2[c]);
            if (dist < bv || (dist == bv && c < bidx)) { bv = dist; bidx = c; }
        }
        rv[tid] = bv; ri[tid] = bidx;
        __syncthreads();
        for (int s = 128; s; s >>= 1) {
            if (tid < s) {
                float v2 = rv[tid + s]; int i2 = ri[tid + s];
                if (v2 < rv[tid] || (v2 == rv[tid] && i2 < ri[tid])) {
                    rv[tid] = v2; ri[tid] = i2;
                }
            }
            __syncthreads();
        }
        if (tid == 0) g_idx[row] = ri[0];
        __syncthreads();
    }
}

// ---------------------------------------------------------------------------

__global__ void scatter_kernel(const float* __restrict__ Z, int N) {
    int warp = (blockIdx.x * blockDim.x + threadIdx.x) >> 5;
    int lane = threadIdx.x & 31;
    if (warp >= N) return;
    int j = g_idx[warp];
    if (lane == 0) atomicAdd(&g_counts[j], 1);
    float4 v = ((const float4*)(Z + (size_t)warp * D))[lane];
    long long base = (long long)j * D + lane * 4;
    unsigned long long* s = (unsigned long long*)g_sumsfx;
    atomicAdd(&s[base + 0], (unsigned long long)(long long)llrintf(v.x * 1048576.0f));
    atomicAdd(&s[base + 1], (unsigned long long)(long long)llrintf(v.y * 1048576.0f));
    atomicAdd(&s[base + 2], (unsigned long long)(long long)llrintf(v.z * 1048576.0f));
    atomicAdd(&s[base + 3], (unsigned long long)(long long)llrintf(v.w * 1048576.0f));
}

__global__ void finalize_kernel(const float* __restrict__ Wold,
                                const float* __restrict__ Cold,
                                float* __restrict__ out_w,
                                float* __restrict__ out_c, int K) {
    int k = blockIdx.x;
    int d = threadIdx.x;
    int cnts = g_counts[k];
    float c_old = Cold[k];
    float c_new = (cnts > 0)
        ? __fadd_rn(__fmul_rn(VQ_ALPHA, c_old), __fmul_rn(VQ_OMA, (float)cnts))
        : c_old;
    if (d == 0) out_c[k] = c_new;
    float w = Wold[(size_t)k * D + d];
    float wn = w;
    if (cnts > 0) {
        float s  = (float)((double)g_sumsfx[(size_t)k * D + d] * (1.0 / 1048576.0));
        float cm = fmaxf(c_new, 1e-12f);
        wn = __fadd_rn(__fmul_rn(VQ_ALPHA, w),
                       __fdiv_rn(__fmul_rn(VQ_OMA, s), cm));
    }
    out_w[(size_t)k * D + d] = wn;
}

__global__ void gather_loss_kernel(const float* __restrict__ Z,
                                   const float* __restrict__ Wn,
                                   float* __restrict__ out_st, int N) {
    int d = threadIdx.x;
    float accl = 0.f;
    for (int n = blockIdx.x; n < N; n += gridDim.x) {
        int j = g_idx[n];
        float w = Wn[(size_t)j * D + d];
        float z = Z[(size_t)n * D + d];
        out_st[(size_t)n * D + d] = __fadd_rn(z, __fsub_rn(w, z));
        float df = __fsub_rn(z, w);
        accl = fmaf(df, df, accl);
    }
    __shared__ float red[4];
    float s = accl;
    #pragma unroll
    for (int off = 16; off; off >>= 1) s += __shfl_xor_sync(0xffffffffu, s, off);
    if ((d & 31) == 0) red[d >> 5] = s;
    __syncthreads();
    if (d == 0) {
        float tot = (red[0] + red[1]) + (red[2] + red[3]);
        atomicAdd(&g_loss, (double)tot);
    }
}

__global__ void loss_write_kernel(float* out_loss, int N) {
    *out_loss = (float)(g_loss / (double)N);
}

// ---------------------------------------------------------------------------

extern "C" void kernel_launch(void* const* d_in, const int* in_sizes, int n_in,
                              void* d_out, int out_size) {
    const float* Z = (const float*)d_in[0];
    const float* W = (const float*)d_in[1];
    const float* C = (const float*)d_in[2];
    const int N = in_sizes[0] / D;       // 65536
    const int K = in_sizes[2];           // 2048

    float* out      = (float*)d_out;
    float* out_st   = out;                           // [N*D]
    float* out_loss = out + (size_t)N * D;           // [1]
    float* out_w    = out_loss + 1;                  // [K*D]
    float* out_c    = out_w + (size_t)K * D;         // [K]

    static bool attr_done = false;
    if (!attr_done) {
        cudaFuncSetAttribute(argmin_hmma_kernel,
                             cudaFuncAttributeMaxDynamicSharedMemorySize, SMEM_ARG);
        attr_done = true;
    }

    zero_kernel<<<256, 256>>>(K);
    prep_kernel<<<((N + K) * 32 + 255) / 256, 256>>>(Z, W, N, K);
    argmin_hmma_kernel<<<N / 128, 256, SMEM_ARG>>>();
    tier1_kernel<<<256, 256>>>(Z, W);
    tier2_kernel<<<128, 256>>>(Z, W);
    scatter_kernel<<<N / 8, 256>>>(Z, N);
    finalize_kernel<<<K, D>>>(W, C, out_w, out_c, K);
    gather_loss_kernel<<<2048, D>>>(Z, out_w, out_st, N);
    loss_write_kernel<<<1, 1>>>(out_loss, N);
}

// round 7
// speedup vs baseline: 1.6560x; 1.0273x over previous
#include <cuda_runtime.h>
#include <cuda_fp16.h>
#include <cstdint>
#include <math_constants.h>

// ---------------------------------------------------------------------------
// spk_vq_vae_resnet — occ-3 HMMA + CSR scatter round.
// argmin: fp16 mma.sync, 64-code tiles, 3 CTAs/SM, top-3 band + 2-tier rescue.
// EMA sums: CSR bucket build + per-code int64 fixed-point gather (order-free,
// deterministic, no 64-bit atomic storm).
// Outputs (concat f32): st_out [N*D], commit_loss [1], w_new [K*D], c_new [K]
// ---------------------------------------------------------------------------

#define VQ_ALPHA 0.99f
#define VQ_OMA   0.01f

constexpr int D    = 128;
constexpr int NMAX = 65536;
constexpr int KMAX = 2048;
constexpr int TCB  = 64;             // codes per B tile
constexpr int NT2  = KMAX / TCB;     // 32 tiles
constexpr float BAND = 1e-3f;

// ---- device scratch -------------------------------------------------------
__device__ __align__(16) __half g_Zh[NMAX * D];
__device__ __align__(16) __half g_Wh[KMAX * D];
__device__ float  g_w2[KMAX];
__device__ int    g_idx[NMAX];
__device__ int    g_f1row[NMAX], g_f1a[NMAX], g_f1b[NMAX];
__device__ int    g_f2row[NMAX];
__device__ int    g_n1, g_n2;
__device__ int    g_counts[KMAX];
__device__ int    g_off[KMAX];
__device__ int    g_cursor[KMAX];
__device__ int    g_bucket[NMAX];
__device__ double g_loss;

// ---- helpers --------------------------------------------------------------
__device__ __forceinline__ uint32_t smem_u32(const void* p) {
    uint32_t a;
    asm("{ .reg .u64 t; cvta.to.shared.u64 t, %1; cvt.u32.u64 %0, t; }"
        : "=r"(a) : "l"(p));
    return a;
}
__device__ __forceinline__ void cp_async16(uint32_t smem_dst, const void* gsrc) {
    asm volatile("cp.async.cg.shared.global [%0], [%1], 16;" :: "r"(smem_dst), "l"(gsrc));
}
__device__ __forceinline__ void cp_commit() { asm volatile("cp.async.commit_group;"); }
template <int NN>
__device__ __forceinline__ void cp_wait() { asm volatile("cp.async.wait_group %0;" :: "n"(NN)); }

__device__ __forceinline__ void ldsm4(uint32_t& r0, uint32_t& r1, uint32_t& r2,
                                      uint32_t& r3, uint32_t addr) {
    asm volatile("ldmatrix.sync.aligned.m8n8.x4.shared.b16 {%0,%1,%2,%3}, [%4];"
                 : "=r"(r0), "=r"(r1), "=r"(r2), "=r"(r3) : "r"(addr));
}
__device__ __forceinline__ void mma16816(float* c, uint32_t a0, uint32_t a1,
                                         uint32_t a2, uint32_t a3,
                                         uint32_t b0, uint32_t b1) {
    asm volatile(
        "mma.sync.aligned.m16n8k16.row.col.f32.f16.f16.f32 "
        "{%0,%1,%2,%3}, {%4,%5,%6,%7}, {%8,%9}, {%0,%1,%2,%3};"
        : "+f"(c[0]), "+f"(c[1]), "+f"(c[2]), "+f"(c[3])
        : "r"(a0), "r"(a1), "r"(a2), "r"(a3), "r"(b0), "r"(b1));
}

// top-3 insert with lowest-index tie preference
__device__ __forceinline__ void ins3(float s, int c,
                                     float& b1, int& i1, float& b2, int& i2,
                                     float& b3, int& i3) {
    if (s < b1 || (s == b1 && c < i1)) {
        b3 = b2; i3 = i2; b2 = b1; i2 = i1; b1 = s; i1 = c;
    } else if (s < b2 || (s == b2 && c < i2)) {
        b3 = b2; i3 = i2; b2 = s; i2 = c;
    } else if (s < b3 || (s == b3 && c < i3)) {
        b3 = s; i3 = c;
    }
}

// ---------------------------------------------------------------------------

__global__ void zero_kernel(int K) {
    int i = blockIdx.x * blockDim.x + threadIdx.x;
    int stride = gridDim.x * blockDim.x;
    for (int j = i; j < K; j += stride) { g_counts[j] = 0; g_cursor[j] = 0; }
    if (i == 0) { g_loss = 0.0; g_n1 = 0; g_n2 = 0; }
}

// fp32 -> fp16 conversion for Z and W; w2 for W rows.
__global__ void prep_kernel(const float* __restrict__ Z,
                            const float* __restrict__ W, int N, int K) {
    int g    = (blockIdx.x * blockDim.x + threadIdx.x) >> 5;
    int lane = threadIdx.x & 31;
    if (g >= N + K) return;
    const float* src;
    __half* dst;
    bool isW = (g >= N);
    if (!isW) { src = Z + (size_t)g * D;        dst = g_Zh + (size_t)g * D; }
    else      { src = W + (size_t)(g - N) * D;  dst = g_Wh + (size_t)(g - N) * D; }
    float4 v = ((const float4*)src)[lane];
    __half2 h01 = __floats2half2_rn(v.x, v.y);
    __half2 h23 = __floats2half2_rn(v.z, v.w);
    uint2 u = { *(uint32_t*)&h01, *(uint32_t*)&h23 };
    *(uint2*)(dst + lane * 4) = u;
    if (isW) {
        float s = 0.f;
        s = fmaf(v.x, v.x, s); s = fmaf(v.y, v.y, s);
        s = fmaf(v.z, v.z, s); s = fmaf(v.w, v.w, s);
        #pragma unroll
        for (int off = 16; off; off >>= 1) s += __shfl_xor_sync(0xffffffffu, s, off);
        if (lane == 0) g_w2[g - N] = s;
    }
}

// ---- fp16 HMMA argmin, 64-code tiles, 3 CTAs/SM ---------------------------
// smem: Zs 32KB | Bs 2x16KB | w2s 8KB = 73728 B -> 3 CTAs (221KB < 227KB)
constexpr int SM_Z  = 0;
constexpr int SM_B0 = 32768;
constexpr int SM_W2 = 65536;
constexpr int SMEM_ARG = SM_W2 + KMAX * 4;   // 73728 bytes

// swizzled chunk store address: row-major rows of 16 chunks (16B each)
__device__ __forceinline__ uint32_t sw_addr(uint32_t base, int r, int c) {
    return base + r * 256 + ((c ^ (r & 7)) << 4);
}

__global__ __launch_bounds__(256, 3)
void argmin_hmma_kernel() {
    extern __shared__ char sm[];
    const uint32_t sb = smem_u32(sm);
    float* w2s = (float*)(sm + SM_W2);
    const int tid  = threadIdx.x;
    const int lane = tid & 31;
    const int wid  = tid >> 5;
    const int warpRow = wid * 16;
    const int row0 = blockIdx.x * 128;

    for (int i = tid; i < KMAX; i += 256) w2s[i] = g_w2[i];

    // group 0: Z tile (2048 chunks) + B tile 0 (1024 chunks)
    for (int i = tid; i < 2048; i += 256) {
        int r = i >> 4, c = i & 15;
        cp_async16(sw_addr(sb + SM_Z, r, c), g_Zh + (size_t)(row0 + r) * D + c * 8);
    }
    for (int i = tid; i < 1024; i += 256) {
        int r = i >> 4, c = i & 15;
        cp_async16(sw_addr(sb + SM_B0, r, c), g_Wh + (size_t)r * D + c * 8);
    }
    cp_commit();
    // group 1: B tile 1
    for (int i = tid; i < 1024; i += 256) {
        int r = i >> 4, c = i & 15;
        cp_async16(sw_addr(sb + SM_B0 + 16384, r, c),
                   g_Wh + (size_t)(TCB + r) * D + c * 8);
    }
    cp_commit();

    float B1[2] = {CUDART_INF_F, CUDART_INF_F};
    float B2[2] = {CUDART_INF_F, CUDART_INF_F};
    float B3[2] = {CUDART_INF_F, CUDART_INF_F};
    int   I1[2] = {0x7fffffff, 0x7fffffff};
    int   I2[2] = {0x7fffffff, 0x7fffffff};
    int   I3[2] = {0x7fffffff, 0x7fffffff};

    const int m  = lane >> 3;
    const int r8 = lane & 7;

    for (int t = 0; t < NT2; t++) {
        if (t < NT2 - 1) cp_wait<1>(); else cp_wait<0>();
        __syncthreads();                       // B[t] visible to all warps
        const uint32_t bbase = sb + SM_B0 + (t & 1) * 16384;

        float acc[8][4];
        #pragma unroll
        for (int f = 0; f < 8; f++)
            #pragma unroll
            for (int q = 0; q < 4; q++) acc[f][q] = 0.f;

        #pragma unroll
        for (int ks = 0; ks < 8; ks++) {
            uint32_t a0, a1, a2, a3;
            {
                int row = warpRow + ((m & 1) << 3) + r8;
                int ch  = 2 * ks + (m >> 1);
                ldsm4(a0, a1, a2, a3, sw_addr(sb + SM_Z, row, ch));
            }
            #pragma unroll
            for (int nf = 0; nf < 8; nf += 2) {
                uint32_t c0, c1, c2, c3;
                {
                    int code = nf * 8 + ((m >> 1) << 3) + r8;
                    int ch   = 2 * ks + (m & 1);
                    ldsm4(c0, c1, c2, c3, sw_addr(bbase, code, ch));
                }
                mma16816(acc[nf],     a0, a1, a2, a3, c0, c1);
                mma16816(acc[nf + 1], a0, a1, a2, a3, c2, c3);
            }
        }

        __syncthreads();                       // all warps done reading B[t]

        // prefetch tile t+2 into this buffer; overlap with epilogue
        if (t < NT2 - 2) {
            const __half* src = g_Wh + (size_t)(t + 2) * TCB * D;
            uint32_t dstb = sb + SM_B0 + (t & 1) * 16384;
            for (int i = tid; i < 1024; i += 256) {
                int r = i >> 4, c = i & 15;
                cp_async16(sw_addr(dstb, r, c), src + (size_t)r * D + c * 8);
            }
            cp_commit();
        }

        // epilogue: score s = w2 - 2*zw
        #pragma unroll
        for (int f = 0; f < 8; f++) {
            int cb0 = t * TCB + f * 8 + 2 * (lane & 3);
            float w2a = w2s[cb0], w2b = w2s[cb0 + 1];
            float s;
            s = fmaf(-2.f, acc[f][0], w2a);
            ins3(s, cb0,     B1[0], I1[0], B2[0], I2[0], B3[0], I3[0]);
            s = fmaf(-2.f, acc[f][1], w2b);
            ins3(s, cb0 + 1, B1[0], I1[0], B2[0], I2[0], B3[0], I3[0]);
            s = fmaf(-2.f, acc[f][2], w2a);
            ins3(s, cb0,     B1[1], I1[1], B2[1], I2[1], B3[1], I3[1]);
            s = fmaf(-2.f, acc[f][3], w2b);
            ins3(s, cb0 + 1, B1[1], I1[1], B2[1], I2[1], B3[1], I3[1]);
        }
    }

    // merge across the 4 lanes of each quad (same rows)
    #pragma unroll
    for (int off = 1; off <= 2; off <<= 1) {
        #pragma unroll
        for (int r = 0; r < 2; r++) {
            float v1 = __shfl_xor_sync(0xffffffffu, B1[r], off);
            int   j1 = __shfl_xor_sync(0xffffffffu, I1[r], off);
            float v2 = __shfl_xor_sync(0xffffffffu, B2[r], off);
            int   j2 = __shfl_xor_sync(0xffffffffu, I2[r], off);
            float v3 = __shfl_xor_sync(0xffffffffu, B3[r], off);
            int   j3 = __shfl_xor_sync(0xffffffffu, I3[r], off);
            ins3(v1, j1, B1[r], I1[r], B2[r], I2[r], B3[r], I3[r]);
            ins3(v2, j2, B1[r], I1[r], B2[r], I2[r], B3[r], I3[r]);
            ins3(v3, j3, B1[r], I1[r], B2[r], I2[r], B3[r], I3[r]);
        }
    }

    if ((lane & 3) == 0) {
        #pragma unroll
        for (int r = 0; r < 2; r++) {
            int row = row0 + warpRow + (lane >> 2) + r * 8;
            g_idx[row] = I1[r];
            if (__fsub_rn(B3[r], B1[r]) < BAND) {
                int p = atomicAdd(&g_n2, 1);
                g_f2row[p] = row;
            } else if (__fsub_rn(B2[r], B1[r]) < BAND) {
                int p = atomicAdd(&g_n1, 1);
                g_f1row[p] = row; g_f1a[p] = I1[r]; g_f1b[p] = I2[r];
            }
        }
    }
}

// ---- tier 1: exact fp32 compare of the two candidates ----------------------
__global__ void tier1_kernel(const float* __restrict__ Z,
                             const float* __restrict__ W) {
    int n1 = g_n1;
    int wg = (blockIdx.x * blockDim.x + threadIdx.x) >> 5;
    int lane = threadIdx.x & 31;
    int nwarps = (gridDim.x * blockDim.x) >> 5;
    for (int e = wg; e < n1; e += nwarps) {
        int row = g_f1row[e], ca = g_f1a[e], cb = g_f1b[e];
        float4 zv = ((const float4*)(Z + (size_t)row * D))[lane];
        float4 av = ((const float4*)(W + (size_t)ca * D))[lane];
        float4 bv = ((const float4*)(W + (size_t)cb * D))[lane];
        float z2 = 0.f, da = 0.f, db = 0.f;
        z2 = fmaf(zv.x, zv.x, z2); z2 = fmaf(zv.y, zv.y, z2);
        z2 = fmaf(zv.z, zv.z, z2); z2 = fmaf(zv.w, zv.w, z2);
        da = fmaf(zv.x, av.x, da); da = fmaf(zv.y, av.y, da);
        da = fmaf(zv.z, av.z, da); da = fmaf(zv.w, av.w, da);
        db = fmaf(zv.x, bv.x, db); db = fmaf(zv.y, bv.y, db);
        db = fmaf(zv.z, bv.z, db); db = fmaf(zv.w, bv.w, db);
        #pragma unroll
        for (int off = 16; off; off >>= 1) {
            z2 += __shfl_xor_sync(0xffffffffu, z2, off);
            da += __shfl_xor_sync(0xffffffffu, da, off);
            db += __shfl_xor_sync(0xffffffffu, db, off);
        }
        if (lane == 0) {
            float dista = __fadd_rn(__fsub_rn(z2, __fmul_rn(2.f, da)), g_w2[ca]);
            float distb = __fadd_rn(__fsub_rn(z2, __fmul_rn(2.f, db)), g_w2[cb]);
            g_idx[row] = (distb < dista || (distb == dista && cb < ca)) ? cb : ca;
        }
    }
}

// ---- tier 2: full-K exact recompute (rare rows) ----------------------------
__global__ void tier2_kernel(const float* __restrict__ Z,
                             const float* __restrict__ W) {
    __shared__ float zrow[D];
    __shared__ float rv[256];
    __shared__ int   ri[256];
    const int tid = threadIdx.x;
    int n2 = g_n2;
    for (int f = blockIdx.x; f < n2; f += gridDim.x) {
        int row = g_f2row[f];
        if (tid < 32) {
            float4 v = ((const float4*)(Z + (size_t)row * D))[tid];
            *(float4*)&zrow[tid * 4] = v;
        }
        __syncthreads();
        float z2 = 0.f;
        #pragma unroll 8
        for (int d = 0; d < D; d++) z2 = __fadd_rn(z2, __fmul_rn(zrow[d], zrow[d]));
        float bv = CUDART_INF_F; int bidx = 0x7fffffff;
        for (int c = tid; c < KMAX; c += 256) {
            const float* w = W + (size_t)c * D;
            float acc = 0.f;
            #pragma unroll 8
            for (int d = 0; d < D; d++) acc = fmaf(zrow[d], w[d], acc);
            float dist = __fadd_rn(__fsub_rn(z2, __fmul_rn(2.f, acc)), g_w2[c]);
            if (dist < bv || (dist == bv && c < bidx)) { bv = dist; bidx = c; }
        }
        rv[tid] = bv; ri[tid] = bidx;
        __syncthreads();
        for (int s = 128; s; s >>= 1) {
            if (tid < s) {
                float v2 = rv[tid + s]; int i2 = ri[tid + s];
                if (v2 < rv[tid] || (v2 == rv[tid] && i2 < ri[tid])) {
                    rv[tid] = v2; ri[tid] = i2;
                }
            }
            __syncthreads();
        }
        if (tid == 0) g_idx[row] = ri[0];
        __syncthreads();
    }
}

// ---- CSR build: count -> prefix -> place ----------------------------------
__global__ void count_kernel(int N) {
    int i = blockIdx.x * blockDim.x + threadIdx.x;
    if (i < N) atomicAdd(&g_counts[g_idx[i]], 1);
}

__global__ void prefix_kernel() {       // single block, 256 threads, K=2048
    __shared__ int part[256];
    int t = threadIdx.x;
    int base = t * 8;
    int loc[8];
    int s = 0;
    #pragma unroll
    for (int i = 0; i < 8; i++) { loc[i] = s; s += g_counts[base + i]; }
    part[t] = s;
    __syncthreads();
    for (int off = 1; off < 256; off <<= 1) {
        int x = (t >= off) ? part[t - off] : 0;
        __syncthreads();
        part[t] += x;
        __syncthreads();
    }
    int excl = part[t] - s;             // exclusive prefix of this chunk
    #pragma unroll
    for (int i = 0; i < 8; i++) g_off[base + i] = excl + loc[i];
}

__global__ void place_kernel(int N) {
    int i = blockIdx.x * blockDim.x + threadIdx.x;
    if (i < N) {
        int j = g_idx[i];
        int slot = atomicAdd(&g_cursor[j], 1);
        g_bucket[g_off[j] + slot] = i;
    }
}

// ---- per-code gather-sum (int64 fixed point, order-free) + EMA finalize ----
__global__ void codesum_kernel(const float* __restrict__ Z,
                               const float* __restrict__ Wold,
                               const float* __restrict__ Cold,
                               float* __restrict__ out_w,
                               float* __restrict__ out_c) {
    int k = blockIdx.x;
    int d = threadIdx.x;
    int cnt = g_counts[k];
    int off = g_off[k];
    float c_old = Cold[k];
    float c_new = (cnt > 0)
        ? __fadd_rn(__fmul_rn(VQ_ALPHA, c_old), __fmul_rn(VQ_OMA, (float)cnt))
        : c_old;
    if (d == 0) out_c[k] = c_new;

    float w = Wold[(size_t)k * D + d];
    float wn = w;
    if (cnt > 0) {
        long long afx = 0;
        int i = 0;
        for (; i + 1 < cnt; i += 2) {
            int r0 = g_bucket[off + i];
            int r1 = g_bucket[off + i + 1];
            afx += (long long)llrintf(Z[(size_t)r0 * D + d] * 1048576.0f)
                 + (long long)llrintf(Z[(size_t)r1 * D + d] * 1048576.0f);
        }
        if (i < cnt) {
            int r0 = g_bucket[off + i];
            afx += (long long)llrintf(Z[(size_t)r0 * D + d] * 1048576.0f);
        }
        float s  = (float)((double)afx * (1.0 / 1048576.0));
        float cm = fmaxf(c_new, 1e-12f);
        wn = __fadd_rn(__fmul_rn(VQ_ALPHA, w),
                       __fdiv_rn(__fmul_rn(VQ_OMA, s), cm));
    }
    out_w[(size_t)k * D + d] = wn;
}

// st_out = z + (w_new[i]-z); commit loss -> double atomic (one per block).
__global__ void gather_loss_kernel(const float* __restrict__ Z,
                                   const float* __restrict__ Wn,
                                   float* __restrict__ out_st, int N) {
    int d   = threadIdx.x & 127;
    int sub = threadIdx.x >> 7;       // 0/1: two rows per iteration
    float accl = 0.f;
    for (int n = blockIdx.x * 2 + sub; n < N; n += gridDim.x * 2) {
        int j = g_idx[n];
        float w = Wn[(size_t)j * D + d];
        float z = Z[(size_t)n * D + d];
        out_st[(size_t)n * D + d] = __fadd_rn(z, __fsub_rn(w, z));
        float df = __fsub_rn(z, w);
        accl = fmaf(df, df, accl);
    }
    __shared__ float red[8];
    float s = accl;
    #pragma unroll
    for (int off = 16; off; off >>= 1) s += __shfl_xor_sync(0xffffffffu, s, off);
    if ((threadIdx.x & 31) == 0) red[threadIdx.x >> 5] = s;
    __syncthreads();
    if (threadIdx.x == 0) {
        float tot = ((red[0] + red[1]) + (red[2] + red[3]))
                  + ((red[4] + red[5]) + (red[6] + red[7]));
        atomicAdd(&g_loss, (double)tot);
    }
}

__global__ void loss_write_kernel(float* out_loss, int N) {
    *out_loss = (float)(g_loss / (double)N);
}

// ---------------------------------------------------------------------------

extern "C" void kernel_launch(void* const* d_in, const int* in_sizes, int n_in,
                              void* d_out, int out_size) {
    const float* Z = (const float*)d_in[0];
    const float* W = (const float*)d_in[1];
    const float* C = (const float*)d_in[2];
    const int N = in_sizes[0] / D;       // 65536
    const int K = in_sizes[2];           // 2048

    float* out      = (float*)d_out;
    float* out_st   = out;                           // [N*D]
    float* out_loss = out + (size_t)N * D;           // [1]
    float* out_w    = out_loss + 1;                  // [K*D]
    float* out_c    = out_w + (size_t)K * D;         // [K]

    static bool attr_done = false;
    if (!attr_done) {
        cudaFuncSetAttribute(argmin_hmma_kernel,
                             cudaFuncAttributeMaxDynamicSharedMemorySize, SMEM_ARG);
        attr_done = true;
    }

    zero_kernel<<<16, 256>>>(K);
    prep_kernel<<<((N + K) * 32 + 255) / 256, 256>>>(Z, W, N, K);
    argmin_hmma_kernel<<<N / 128, 256, SMEM_ARG>>>();
    tier1_kernel<<<256, 256>>>(Z, W);
    tier2_kernel<<<128, 256>>>(Z, W);
    count_kernel<<<N / 256, 256>>>(N);
    prefix_kernel<<<1, 256>>>();
    place_kernel<<<N / 256, 256>>>(N);
    codesum_kernel<<<K, D>>>(Z, W, C, out_w, out_c);
    gather_loss_kernel<<<2048, 256>>>(Z, out_w, out_st, N);
    loss_write_kernel<<<1, 1>>>(out_loss, N);
}